// round 13
// baseline (speedup 1.0000x reference)
#include <cuda_runtime.h>

#define Fdim 60
#define Mdim 600
#define OUTd 18
#define NTHR 512
#define SR   68                 // x-tile row stride; 68 % 32 == 4 -> conflict-free patterns
#define XTSZ (120 * SR)         // 8160 floats per x buffer

typedef unsigned long long u64;

__device__ __forceinline__ u64 pk2(float x, float y) {
    u64 r; asm("mov.b64 %0,{%1,%2};" : "=l"(r) : "f"(x), "f"(y)); return r;
}
__device__ __forceinline__ float2 upk2(u64 v) {
    float2 r; asm("mov.b64 {%0,%1},%2;" : "=f"(r.x), "=f"(r.y) : "l"(v)); return r;
}
__device__ __forceinline__ u64 ffma2(u64 a, u64 b, u64 c) {
    u64 d; asm("fma.rn.f32x2 %0,%1,%2,%3;" : "=l"(d) : "l"(a), "l"(b), "l"(c)); return d;
}
__device__ __forceinline__ u64 fadd2(u64 a, u64 b) {
    u64 d; asm("add.rn.f32x2 %0,%1,%2;" : "=l"(d) : "l"(a), "l"(b)); return d;
}

// Distributed reduction over 4 lanes (xor 1,2): lane aj ends with accumulator aj
// fully reduced across its 4-lane group.
__device__ __forceinline__ u64 distred4(u64 a0, u64 a1, u64 a2, u64 a3, int aj) {
    u64 u = (aj & 1) ? a1 : a0;
    u64 v = (aj & 1) ? a0 : a1;
    u = fadd2(u, __shfl_xor_sync(0xffffffffu, v, 1));
    u64 w2 = (aj & 1) ? a3 : a2;
    u64 z  = (aj & 1) ? a2 : a3;
    w2 = fadd2(w2, __shfl_xor_sync(0xffffffffu, z, 1));
    u64 r = (aj & 2) ? w2 : u;
    u64 s = (aj & 2) ? u : w2;
    r = fadd2(r, __shfl_xor_sync(0xffffffffu, s, 2));
    return r;
}

// smem layout (floats): 3 x-buffers | 2 act buffers | W | apart | q1p | q2p | msc
#define SM_FLOATS (3 * XTSZ + 2 * 960 + 480 + 64 + 120 + 16 + 18)

__global__ __launch_bounds__(NTHR, 2)
void netfv_kernel(const float* __restrict__ gx,     // [B*600, 60]
                  const float* __restrict__ gW,     // [60, 8]
                  const float* __restrict__ gcov,   // [60, 8]
                  const float* __restrict__ gbias,  // [8]
                  const float* __restrict__ gw2,    // [60, 8]
                  const float* __restrict__ gH,     // [960, 18]
                  float* __restrict__ gout)         // [B, 18]
{
    extern __shared__ __align__(16) float sm[];
    float* bxa = sm;
    float* bxb = sm + XTSZ;
    float* bxc = sm + 2 * XTSZ;
    float* ac0 = sm + 3 * XTSZ;           // 960
    float* ac1 = ac0 + 960;               // 960
    float* sW  = ac1 + 960;               // 480
    float* s_apart = sW + 480;            // 64  (8 A-warps x 8c)
    float* s_q1p   = s_apart + 64;        // 120 (15 warps x 8c)
    float* s_q2p   = s_q1p + 120;         // 16
    float* s_msc   = s_q2p + 16;          // 18: [0..7]=asum,[8..15]=rc,[16]=rg,[17]=sc2

    const int tid  = threadIdx.x;
    const int b    = blockIdx.x;
    const int w    = tid >> 5;
    const int lane = tid & 31;

    if (tid < 480) sW[tid] = gW[tid];

    const float* xb = gx + (size_t)b * (Mdim * Fdim);

    // staging mapping (contiguous): sid in 0..239 per group; elem e = sid + 240j,
    // j = 0..29 -> m = md + 4j, f = fd.  A-group stages j=0..13; B-group j=14..29.
    const int sid   = (w < 8) ? tid : (tid - 256);
    const bool sidv = (sid >= 0) && (sid < 240);
    const int md    = sidv ? sid / 60 : 0;
    const int fd    = sidv ? sid - md * 60 : 0;
    const int stoff = md * SR + fd;

    // prologue: B-group stages ALL 30 elements of chunk 0
    if (w >= 8 && sidv) {
        const float* src = xb + sid;
        float* dst = bxa + stoff;
#pragma unroll
        for (int jb = 0; jb < 3; jb++) {
            float t[10];
#pragma unroll
            for (int q = 0; q < 10; q++) t[q] = src[(jb * 10 + q) * 240];
#pragma unroll
            for (int q = 0; q < 10; q++) dst[(jb * 10 + q) * 4 * SR] = t[q];
        }
    }
    __syncthreads();

    // phase-A mapping (warps 0..7, all 256 threads run shfls):
    // rp = tid>>2 in 0..63, valid rows rp<60; rows rp and rp+60; aj = k-quarter
    const int rp   = tid >> 2;
    const int aj   = tid & 3;
    const bool rpv = (rp < 60);
    const int rpc  = rpv ? rp : 59;        // clamped for loads
    const float2 bp = __ldg((const float2*)gbias + aj);   // this lane's bias c-pair
    float asr0 = 0.f, asr1 = 0.f;

    // phase-B mapping: warps 8..15, g = w-8, f = lane (<30) and lane+30
    const int g  = w - 8;
    const int fl = lane;

    u64 c1a[4], c2a[4], c1b[4], c2b[4];
#pragma unroll
    for (int p = 0; p < 4; p++) { c1a[p]=0; c2a[p]=0; c1b[p]=0; c2b[p]=0; }

    float* xA = bxa;   // phase-A buffer (chunk it)
    float* xN = bxb;   // staging target (chunk it+1)
    float* xB = bxc;   // phase-B buffer (chunk it-1)

    for (int it = 0; it < 6; ++it) {
        float* acW = (it & 1) ? ac1 : ac0;
        float* acR = (it & 1) ? ac0 : ac1;
        const bool dostg = (it < 4) && sidv;

        if (w < 8) {
            // ---- A-group staging loads j=0..13 (latency hidden behind phase A) ----
            float st[14];
            if (dostg) {
                const float* src = xb + (it + 1) * 7200 + sid;
#pragma unroll
                for (int j = 0; j < 14; j++) st[j] = src[j * 240];
            }
            // ---- phase A on chunk it (ALL 256 threads; guarded stores) ----
            if (it < 5) {
                u64 a0[4], a1[4];
#pragma unroll
                for (int p = 0; p < 4; p++) { a0[p] = 0; a1[p] = 0; }
                const float* x0 = xA + rpc * SR + aj;
                const float* x1 = x0 + 60 * SR;
#pragma unroll
                for (int i = 0; i < 15; i++) {
                    int kk = aj + 4 * i;               // interleaved k -> conflict-free
                    float xk0 = x0[4 * i];
                    float xk1 = x1[4 * i];
                    ulonglong2 wA = *(const ulonglong2*)&sW[kk * 8];
                    ulonglong2 wB = *(const ulonglong2*)&sW[kk * 8 + 4];
                    u64 X0 = pk2(xk0, xk0), X1 = pk2(xk1, xk1);
                    a0[0] = ffma2(X0, wA.x, a0[0]);  a1[0] = ffma2(X1, wA.x, a1[0]);
                    a0[1] = ffma2(X0, wA.y, a0[1]);  a1[1] = ffma2(X1, wA.y, a1[1]);
                    a0[2] = ffma2(X0, wB.x, a0[2]);  a1[2] = ffma2(X1, wB.x, a1[2]);
                    a0[3] = ffma2(X0, wB.y, a0[3]);  a1[3] = ffma2(X1, wB.y, a1[3]);
                }
                // distributed 4-lane reduction: lane aj owns c-pair (2aj, 2aj+1)
                u64 r0 = distred4(a0[0], a0[1], a0[2], a0[3], aj);
                u64 r1 = distred4(a1[0], a1[1], a1[2], a1[3], aj);
                // softmax (no max-sub: logits bounded, __expf safe)
                {
                    float2 p0 = upk2(r0);
                    float e0 = __expf(p0.x + bp.x);
                    float e1 = __expf(p0.y + bp.y);
                    float s2 = e0 + e1;
                    s2 += __shfl_xor_sync(0xffffffffu, s2, 1);
                    s2 += __shfl_xor_sync(0xffffffffu, s2, 2);
                    float inv = __fdividef(1.f, s2);
                    if (rpv) {
                        float v0 = e0 * inv, v1 = e1 * inv;
                        *(float2*)&acW[rp * 8 + 2 * aj] = make_float2(v0, v1);
                        asr0 += v0; asr1 += v1;
                    }
                }
                {
                    float2 p1 = upk2(r1);
                    float e0 = __expf(p1.x + bp.x);
                    float e1 = __expf(p1.y + bp.y);
                    float s2 = e0 + e1;
                    s2 += __shfl_xor_sync(0xffffffffu, s2, 1);
                    s2 += __shfl_xor_sync(0xffffffffu, s2, 2);
                    float inv = __fdividef(1.f, s2);
                    if (rpv) {
                        float v0 = e0 * inv, v1 = e1 * inv;
                        *(float2*)&acW[(rp + 60) * 8 + 2 * aj] = make_float2(v0, v1);
                        asr0 += v0; asr1 += v1;
                    }
                }
            }
            // commit A-group staged elements j=0..13
            if (dostg) {
                float* dst = xN + stoff;
#pragma unroll
                for (int j = 0; j < 14; j++) dst[j * 4 * SR] = st[j];
            }
        } else {
            // ---- B-group staging j=14..29 (two blocks of 8) ----
            if (dostg) {
                const float* src = xb + (it + 1) * 7200 + sid;
                float* dst = xN + stoff;
#pragma unroll
                for (int jb = 0; jb < 2; jb++) {
                    float t[8];
#pragma unroll
                    for (int q = 0; q < 8; q++) t[q] = src[(14 + jb * 8 + q) * 240];
#pragma unroll
                    for (int q = 0; q < 8; q++) dst[(14 + jb * 8 + q) * 4 * SR] = t[q];
                }
            }
            // ---- phase B on chunk it-1: fv1/fv2, 2 f per thread (no shfls) ----
            if (it >= 1 && lane < 30) {
#pragma unroll
                for (int i = 0; i < 15; i++) {
                    int m = g + 8 * i;
                    ulonglong2 A01 = *(const ulonglong2*)&acR[m * 8];
                    ulonglong2 A23 = *(const ulonglong2*)&acR[m * 8 + 4];
                    float xa = xB[m * SR + fl];
                    float xv = xB[m * SR + fl + 30];
                    u64 XA = pk2(xa, xa), XB = pk2(xv, xv);
                    float qa = xa * xa, qb = xv * xv;
                    u64 QA = pk2(qa, qa), QB = pk2(qb, qb);
                    c1a[0] = ffma2(A01.x, XA, c1a[0]);  c2a[0] = ffma2(A01.x, QA, c2a[0]);
                    c1a[1] = ffma2(A01.y, XA, c1a[1]);  c2a[1] = ffma2(A01.y, QA, c2a[1]);
                    c1a[2] = ffma2(A23.x, XA, c1a[2]);  c2a[2] = ffma2(A23.x, QA, c2a[2]);
                    c1a[3] = ffma2(A23.y, XA, c1a[3]);  c2a[3] = ffma2(A23.y, QA, c2a[3]);
                    c1b[0] = ffma2(A01.x, XB, c1b[0]);  c2b[0] = ffma2(A01.x, QB, c2b[0]);
                    c1b[1] = ffma2(A01.y, XB, c1b[1]);  c2b[1] = ffma2(A01.y, QB, c2b[1]);
                    c1b[2] = ffma2(A23.x, XB, c1b[2]);  c2b[2] = ffma2(A23.x, QB, c2b[2]);
                    c1b[3] = ffma2(A23.y, XB, c1b[3]);  c2b[3] = ffma2(A23.y, QB, c2b[3]);
                }
            }
        }
        __syncthreads();
        // rotate x buffers: {A, N, B} <- {N, B, A}
        float* t = xA; xA = xN; xN = xB; xB = t;
    }

    // ================= epilogue =================
    float* s_red = bxa;            // 3840
    float* s_fv  = bxa + 3840;     // 960
    float* s_pt  = bxa + 4800;     // 486

    // a_sum partials from A-warps (ALL 256 threads run the shfls)
    if (w < 8) {
        float r0 = asr0, r1 = asr1;
        r0 += __shfl_xor_sync(0xffffffffu, r0, 4);
        r1 += __shfl_xor_sync(0xffffffffu, r1, 4);
        r0 += __shfl_xor_sync(0xffffffffu, r0, 8);
        r1 += __shfl_xor_sync(0xffffffffu, r1, 8);
        r0 += __shfl_xor_sync(0xffffffffu, r0, 16);
        r1 += __shfl_xor_sync(0xffffffffu, r1, 16);
        if (lane < 4) {
            s_apart[w * 8 + 2 * aj]     = r0;
            s_apart[w * 8 + 2 * aj + 1] = r1;
        }
    }
    // dump acc1 for both f
    if (w >= 8 && lane < 30) {
        int vt0 = g * 60 + fl;
        float2 q0 = upk2(c1a[0]), q1 = upk2(c1a[1]), q2v = upk2(c1a[2]), q3 = upk2(c1a[3]);
        float4* rp0 = (float4*)&s_red[vt0 * 8];
        rp0[0] = make_float4(q0.x, q0.y, q1.x, q1.y);
        rp0[1] = make_float4(q2v.x, q2v.y, q3.x, q3.y);
        q0 = upk2(c1b[0]); q1 = upk2(c1b[1]); q2v = upk2(c1b[2]); q3 = upk2(c1b[3]);
        float4* rp1 = (float4*)&s_red[(vt0 + 30) * 8];
        rp1[0] = make_float4(q0.x, q0.y, q1.x, q1.y);
        rp1[1] = make_float4(q2v.x, q2v.y, q3.x, q3.y);
    }
    __syncthreads();
    if (tid < 8) {
        float A = 0.f;
#pragma unroll
        for (int ww = 0; ww < 8; ww++) A += s_apart[ww * 8 + tid];
        s_msc[tid] = A;
    }
    float fv1raw = 0.f, fv2raw = 0.f;
    if (tid < 480) {
#pragma unroll
        for (int gg = 0; gg < 8; gg++) fv1raw += s_red[gg * 480 + tid];
    }
    __syncthreads();
    if (w >= 8 && lane < 30) {
        int vt0 = g * 60 + fl;
        float2 q0 = upk2(c2a[0]), q1 = upk2(c2a[1]), q2v = upk2(c2a[2]), q3 = upk2(c2a[3]);
        float4* rp0 = (float4*)&s_red[vt0 * 8];
        rp0[0] = make_float4(q0.x, q0.y, q1.x, q1.y);
        rp0[1] = make_float4(q2v.x, q2v.y, q3.x, q3.y);
        q0 = upk2(c2b[0]); q1 = upk2(c2b[1]); q2v = upk2(c2b[2]); q3 = upk2(c2b[3]);
        float4* rp1 = (float4*)&s_red[(vt0 + 30) * 8];
        rp1[0] = make_float4(q0.x, q0.y, q1.x, q1.y);
        rp1[1] = make_float4(q2v.x, q2v.y, q3.x, q3.y);
    }
    __syncthreads();

    float fv1 = 0.f, fv2 = 0.f;
    if (tid < 480) {                                  // warps 0..14, warp-aligned
#pragma unroll
        for (int gg = 0; gg < 8; gg++) fv2raw += s_red[gg * 480 + tid];
        const int c2i = tid & 7;
        float Asum = s_msc[c2i];
        float w2v  = __ldg(gw2 + tid);
        float cv   = __ldg(gcov + tid);
        float cw   = cv * cv + 1e-6f;
        fv1 = (fv1raw - Asum * w2v) / cw;
        fv2 = (Asum * w2v * w2v + fv2raw - 2.f * fv1raw * w2v) / (cw * cw) - Asum;

        float sq1 = fv1 * fv1;
        float sq2 = fv2 * fv2;
        sq1 += __shfl_xor_sync(0xffffffffu, sq1, 8);
        sq1 += __shfl_xor_sync(0xffffffffu, sq1, 16);
        sq2 += __shfl_xor_sync(0xffffffffu, sq2, 1);
        sq2 += __shfl_xor_sync(0xffffffffu, sq2, 2);
        sq2 += __shfl_xor_sync(0xffffffffu, sq2, 4);
        sq2 += __shfl_xor_sync(0xffffffffu, sq2, 8);
        sq2 += __shfl_xor_sync(0xffffffffu, sq2, 16);
        if (lane < 8)  s_q1p[w * 8 + lane] = sq1;
        if (lane == 0) s_q2p[w] = sq2;
    }
    __syncthreads();
    if (tid == 0) {
        float G = 0.f;
#pragma unroll
        for (int c = 0; c < 8; c++) {
            float q = 0.f;
#pragma unroll
            for (int ww = 0; ww < 15; ww++) q += s_q1p[ww * 8 + c];
            float r = rsqrtf(fmaxf(q, 1e-12f));
            s_msc[8 + c] = r;
            G += q * r * r;
        }
        s_msc[16] = rsqrtf(fmaxf(G, 1e-12f));
        float q2s = 0.f;
#pragma unroll
        for (int ww = 0; ww < 15; ww++) q2s += s_q2p[ww];
        float r2  = rsqrtf(fmaxf(q2s, 1e-12f));
        float q2b = q2s * r2 * r2;
        s_msc[17] = r2 * rsqrtf(fmaxf(q2b, 1e-12f));
    }
    __syncthreads();
    if (tid < 480) {
        s_fv[tid]       = fv1 * s_msc[8 + (tid & 7)] * s_msc[16];
        s_fv[480 + tid] = fv2 * s_msc[17];
    }
    __syncthreads();

    // final matvec: out[b,:] = fv(960) @ H(960x18)
    if (tid < 486) {
        int ggq = tid / 18;
        int o   = tid - ggq * 18;
        float acc = 0.f;
        for (int jj = ggq; jj < 960; jj += 27)
            acc += s_fv[jj] * gH[jj * 18 + o];
        s_pt[tid] = acc;
    }
    __syncthreads();
    if (tid < 18) {
        float s = 0.f;
#pragma unroll
        for (int ggq = 0; ggq < 27; ggq++) s += s_pt[ggq * 18 + tid];
        gout[b * OUTd + tid] = s;
    }
}

extern "C" void kernel_launch(void* const* d_in, const int* in_sizes, int n_in,
                              void* d_out, int out_size) {
    const float* x    = (const float*)d_in[0];
    const float* W    = (const float*)d_in[1];
    const float* cov  = (const float*)d_in[2];
    const float* bias = (const float*)d_in[3];
    const float* w2   = (const float*)d_in[4];
    const float* H    = (const float*)d_in[5];
    float* out = (float*)d_out;

    const int smem_bytes = SM_FLOATS * 4;   // ~108 KB
    cudaFuncSetAttribute(netfv_kernel, cudaFuncAttributeMaxDynamicSharedMemorySize, smem_bytes);

    int B = in_sizes[0] / (Mdim * Fdim);    // 2048
    netfv_kernel<<<B, NTHR, smem_bytes>>>(x, W, cov, bias, w2, H, out);
}

// round 14
// speedup vs baseline: 1.0703x; 1.0703x over previous
#include <cuda_runtime.h>

#define Fdim 60
#define Mdim 600
#define OUTd 18
#define NTHR 512
#define SR   68                 // x-tile row stride; 68 % 32 == 4 -> conflict-free patterns
#define XTSZ (120 * SR)         // 8160 floats per x buffer

typedef unsigned long long u64;

__device__ __forceinline__ u64 pk2(float x, float y) {
    u64 r; asm("mov.b64 %0,{%1,%2};" : "=l"(r) : "f"(x), "f"(y)); return r;
}
__device__ __forceinline__ float2 upk2(u64 v) {
    float2 r; asm("mov.b64 {%0,%1},%2;" : "=f"(r.x), "=f"(r.y) : "l"(v)); return r;
}
__device__ __forceinline__ u64 ffma2(u64 a, u64 b, u64 c) {
    u64 d; asm("fma.rn.f32x2 %0,%1,%2,%3;" : "=l"(d) : "l"(a), "l"(b), "l"(c)); return d;
}
__device__ __forceinline__ u64 fadd2(u64 a, u64 b) {
    u64 d; asm("add.rn.f32x2 %0,%1,%2;" : "=l"(d) : "l"(a), "l"(b)); return d;
}

// Distributed reduction over 4 lanes (xor 1,2): lane aj ends with accumulator aj
// fully reduced across its 4-lane group.
__device__ __forceinline__ u64 distred4(u64 a0, u64 a1, u64 a2, u64 a3, int aj) {
    u64 u = (aj & 1) ? a1 : a0;
    u64 v = (aj & 1) ? a0 : a1;
    u = fadd2(u, __shfl_xor_sync(0xffffffffu, v, 1));
    u64 w2 = (aj & 1) ? a3 : a2;
    u64 z  = (aj & 1) ? a2 : a3;
    w2 = fadd2(w2, __shfl_xor_sync(0xffffffffu, z, 1));
    u64 r = (aj & 2) ? w2 : u;
    u64 s = (aj & 2) ? u : w2;
    r = fadd2(r, __shfl_xor_sync(0xffffffffu, s, 2));
    return r;
}

// smem layout (floats): 3 x-buffers | 2 act buffers | W | apart | q1p | q2p | msc
#define SM_FLOATS (3 * XTSZ + 2 * 960 + 480 + 64 + 120 + 16 + 18)

__global__ __launch_bounds__(NTHR, 2)
void netfv_kernel(const float* __restrict__ gx,     // [B*600, 60]
                  const float* __restrict__ gW,     // [60, 8]
                  const float* __restrict__ gcov,   // [60, 8]
                  const float* __restrict__ gbias,  // [8]
                  const float* __restrict__ gw2,    // [60, 8]
                  const float* __restrict__ gH,     // [960, 18]
                  float* __restrict__ gout)         // [B, 18]
{
    extern __shared__ __align__(16) float sm[];
    float* bxa = sm;
    float* bxb = sm + XTSZ;
    float* bxc = sm + 2 * XTSZ;
    float* ac0 = sm + 3 * XTSZ;           // 960
    float* ac1 = ac0 + 960;               // 960
    float* sW  = ac1 + 960;               // 480
    float* s_apart = sW + 480;            // 64  (8 A-warps x 8c)
    float* s_q1p   = s_apart + 64;        // 120 (15 warps x 8c)
    float* s_q2p   = s_q1p + 120;         // 16
    float* s_msc   = s_q2p + 16;          // 18: [0..7]=asum,[8..15]=rc,[16]=rg,[17]=sc2

    const int tid  = threadIdx.x;
    const int b    = blockIdx.x;
    const int w    = tid >> 5;
    const int lane = tid & 31;

    if (tid < 480) sW[tid] = gW[tid];

    const float* xb = gx + (size_t)b * (Mdim * Fdim);

    // staging mapping on B-warps (cp.async, 8B per op):
    // sid = tid-256 in 0..239; md = sid/30 (0..7), fp = sid%30;
    // copies x[(md+8j)*60 + 2fp .. +1] for j = 0..14  (covers all 120 rows x 60 f)
    const int sid   = tid - 256;
    const bool stgv = (w >= 8) && (sid < 240);
    const int md2   = stgv ? sid / 30 : 0;
    const int fp    = stgv ? sid - md2 * 30 : 0;
    const int soff  = md2 * 60 + 2 * fp;          // gmem float offset of j=0 element
    const int doff  = md2 * SR + 2 * fp;          // smem float offset of j=0 element

    // prologue: B-group stages chunk 0 via cp.async
    if (stgv) {
        const float* src = xb + soff;
        unsigned int dst = (unsigned int)__cvta_generic_to_shared(bxa + doff);
#pragma unroll
        for (int j = 0; j < 15; j++) {
            asm volatile("cp.async.ca.shared.global [%0], [%1], 8;"
                         :: "r"(dst + j * 8 * SR * 4), "l"(src + j * 8 * 60) : "memory");
        }
        asm volatile("cp.async.commit_group;" ::: "memory");
        asm volatile("cp.async.wait_group 0;" ::: "memory");
    }
    __syncthreads();

    // phase-A mapping (warps 0..7, all 256 threads run shfls):
    // rp = tid>>2 in 0..63, valid rows rp<60; rows rp and rp+60; aj = k-quarter
    const int rp   = tid >> 2;
    const int aj   = tid & 3;
    const bool rpv = (rp < 60);
    const int rpc  = rpv ? rp : 59;        // clamped for loads
    const float2 bp = __ldg((const float2*)gbias + aj);   // this lane's bias c-pair
    float asr0 = 0.f, asr1 = 0.f;

    // phase-B mapping: warps 8..15, g = w-8, f = lane (<30) and lane+30
    const int g  = w - 8;
    const int fl = lane;

    u64 c1a[4], c2a[4], c1b[4], c2b[4];
#pragma unroll
    for (int p = 0; p < 4; p++) { c1a[p]=0; c2a[p]=0; c1b[p]=0; c2b[p]=0; }

    float* xA = bxa;   // phase-A buffer (chunk it)
    float* xN = bxb;   // staging target (chunk it+1)
    float* xB = bxc;   // phase-B buffer (chunk it-1)

    for (int it = 0; it < 6; ++it) {
        float* acW = (it & 1) ? ac1 : ac0;
        float* acR = (it & 1) ? ac0 : ac1;
        const bool dostg = (it < 4) && stgv;

        if (w < 8) {
            // ---- phase A on chunk it (ALL 256 threads; guarded stores) ----
            if (it < 5) {
                u64 a0[4], a1[4];
#pragma unroll
                for (int p = 0; p < 4; p++) { a0[p] = 0; a1[p] = 0; }
                const float* x0 = xA + rpc * SR + aj;
                const float* x1 = x0 + 60 * SR;
#pragma unroll
                for (int i = 0; i < 15; i++) {
                    int kk = aj + 4 * i;               // interleaved k -> conflict-free
                    float xk0 = x0[4 * i];
                    float xk1 = x1[4 * i];
                    ulonglong2 wA = *(const ulonglong2*)&sW[kk * 8];
                    ulonglong2 wB = *(const ulonglong2*)&sW[kk * 8 + 4];
                    u64 X0 = pk2(xk0, xk0), X1 = pk2(xk1, xk1);
                    a0[0] = ffma2(X0, wA.x, a0[0]);  a1[0] = ffma2(X1, wA.x, a1[0]);
                    a0[1] = ffma2(X0, wA.y, a0[1]);  a1[1] = ffma2(X1, wA.y, a1[1]);
                    a0[2] = ffma2(X0, wB.x, a0[2]);  a1[2] = ffma2(X1, wB.x, a1[2]);
                    a0[3] = ffma2(X0, wB.y, a0[3]);  a1[3] = ffma2(X1, wB.y, a1[3]);
                }
                // distributed 4-lane reduction: lane aj owns c-pair (2aj, 2aj+1)
                u64 r0 = distred4(a0[0], a0[1], a0[2], a0[3], aj);
                u64 r1 = distred4(a1[0], a1[1], a1[2], a1[3], aj);
                // softmax (no max-sub: logits bounded, __expf safe)
                {
                    float2 p0 = upk2(r0);
                    float e0 = __expf(p0.x + bp.x);
                    float e1 = __expf(p0.y + bp.y);
                    float s2 = e0 + e1;
                    s2 += __shfl_xor_sync(0xffffffffu, s2, 1);
                    s2 += __shfl_xor_sync(0xffffffffu, s2, 2);
                    float inv = __fdividef(1.f, s2);
                    if (rpv) {
                        float v0 = e0 * inv, v1 = e1 * inv;
                        *(float2*)&acW[rp * 8 + 2 * aj] = make_float2(v0, v1);
                        asr0 += v0; asr1 += v1;
                    }
                }
                {
                    float2 p1 = upk2(r1);
                    float e0 = __expf(p1.x + bp.x);
                    float e1 = __expf(p1.y + bp.y);
                    float s2 = e0 + e1;
                    s2 += __shfl_xor_sync(0xffffffffu, s2, 1);
                    s2 += __shfl_xor_sync(0xffffffffu, s2, 2);
                    float inv = __fdividef(1.f, s2);
                    if (rpv) {
                        float v0 = e0 * inv, v1 = e1 * inv;
                        *(float2*)&acW[(rp + 60) * 8 + 2 * aj] = make_float2(v0, v1);
                        asr0 += v0; asr1 += v1;
                    }
                }
            }
        } else {
            // ---- issue cp.async staging for chunk it+1 (latency hidden by FMA loop) ----
            if (dostg) {
                const float* src = xb + (it + 1) * 7200 + soff;
                unsigned int dst = (unsigned int)__cvta_generic_to_shared(xN + doff);
#pragma unroll
                for (int j = 0; j < 15; j++) {
                    asm volatile("cp.async.ca.shared.global [%0], [%1], 8;"
                                 :: "r"(dst + j * 8 * SR * 4), "l"(src + j * 8 * 60) : "memory");
                }
                asm volatile("cp.async.commit_group;" ::: "memory");
            }
            // ---- phase B on chunk it-1: fv1/fv2, 2 f per thread (no shfls) ----
            if (it >= 1 && lane < 30) {
#pragma unroll
                for (int i = 0; i < 15; i++) {
                    int m = g + 8 * i;
                    ulonglong2 A01 = *(const ulonglong2*)&acR[m * 8];
                    ulonglong2 A23 = *(const ulonglong2*)&acR[m * 8 + 4];
                    float xa = xB[m * SR + fl];
                    float xv = xB[m * SR + fl + 30];
                    u64 XA = pk2(xa, xa), XB = pk2(xv, xv);
                    float qa = xa * xa, qb = xv * xv;
                    u64 QA = pk2(qa, qa), QB = pk2(qb, qb);
                    c1a[0] = ffma2(A01.x, XA, c1a[0]);  c2a[0] = ffma2(A01.x, QA, c2a[0]);
                    c1a[1] = ffma2(A01.y, XA, c1a[1]);  c2a[1] = ffma2(A01.y, QA, c2a[1]);
                    c1a[2] = ffma2(A23.x, XA, c1a[2]);  c2a[2] = ffma2(A23.x, QA, c2a[2]);
                    c1a[3] = ffma2(A23.y, XA, c1a[3]);  c2a[3] = ffma2(A23.y, QA, c2a[3]);
                    c1b[0] = ffma2(A01.x, XB, c1b[0]);  c2b[0] = ffma2(A01.x, QB, c2b[0]);
                    c1b[1] = ffma2(A01.y, XB, c1b[1]);  c2b[1] = ffma2(A01.y, QB, c2b[1]);
                    c1b[2] = ffma2(A23.x, XB, c1b[2]);  c2b[2] = ffma2(A23.x, QB, c2b[2]);
                    c1b[3] = ffma2(A23.y, XB, c1b[3]);  c2b[3] = ffma2(A23.y, QB, c2b[3]);
                }
            }
            // drain cp.async before the barrier publishes xN to A-warps
            if (dostg) {
                asm volatile("cp.async.wait_group 0;" ::: "memory");
            }
        }
        __syncthreads();
        // rotate x buffers: {A, N, B} <- {N, B, A}
        float* t = xA; xA = xN; xN = xB; xB = t;
    }

    // ================= epilogue =================
    float* s_red = bxa;            // 3840
    float* s_fv  = bxa + 3840;     // 960
    float* s_pt  = bxa + 4800;     // 486

    // a_sum partials from A-warps (ALL 256 threads run the shfls)
    if (w < 8) {
        float r0 = asr0, r1 = asr1;
        r0 += __shfl_xor_sync(0xffffffffu, r0, 4);
        r1 += __shfl_xor_sync(0xffffffffu, r1, 4);
        r0 += __shfl_xor_sync(0xffffffffu, r0, 8);
        r1 += __shfl_xor_sync(0xffffffffu, r1, 8);
        r0 += __shfl_xor_sync(0xffffffffu, r0, 16);
        r1 += __shfl_xor_sync(0xffffffffu, r1, 16);
        if (lane < 4) {
            s_apart[w * 8 + 2 * aj]     = r0;
            s_apart[w * 8 + 2 * aj + 1] = r1;
        }
    }
    // dump acc1 for both f
    if (w >= 8 && lane < 30) {
        int vt0 = g * 60 + fl;
        float2 q0 = upk2(c1a[0]), q1 = upk2(c1a[1]), q2v = upk2(c1a[2]), q3 = upk2(c1a[3]);
        float4* rp0 = (float4*)&s_red[vt0 * 8];
        rp0[0] = make_float4(q0.x, q0.y, q1.x, q1.y);
        rp0[1] = make_float4(q2v.x, q2v.y, q3.x, q3.y);
        q0 = upk2(c1b[0]); q1 = upk2(c1b[1]); q2v = upk2(c1b[2]); q3 = upk2(c1b[3]);
        float4* rp1 = (float4*)&s_red[(vt0 + 30) * 8];
        rp1[0] = make_float4(q0.x, q0.y, q1.x, q1.y);
        rp1[1] = make_float4(q2v.x, q2v.y, q3.x, q3.y);
    }
    __syncthreads();
    if (tid < 8) {
        float A = 0.f;
#pragma unroll
        for (int ww = 0; ww < 8; ww++) A += s_apart[ww * 8 + tid];
        s_msc[tid] = A;
    }
    float fv1raw = 0.f, fv2raw = 0.f;
    if (tid < 480) {
#pragma unroll
        for (int gg = 0; gg < 8; gg++) fv1raw += s_red[gg * 480 + tid];
    }
    __syncthreads();
    if (w >= 8 && lane < 30) {
        int vt0 = g * 60 + fl;
        float2 q0 = upk2(c2a[0]), q1 = upk2(c2a[1]), q2v = upk2(c2a[2]), q3 = upk2(c2a[3]);
        float4* rp0 = (float4*)&s_red[vt0 * 8];
        rp0[0] = make_float4(q0.x, q0.y, q1.x, q1.y);
        rp0[1] = make_float4(q2v.x, q2v.y, q3.x, q3.y);
        q0 = upk2(c2b[0]); q1 = upk2(c2b[1]); q2v = upk2(c2b[2]); q3 = upk2(c2b[3]);
        float4* rp1 = (float4*)&s_red[(vt0 + 30) * 8];
        rp1[0] = make_float4(q0.x, q0.y, q1.x, q1.y);
        rp1[1] = make_float4(q2v.x, q2v.y, q3.x, q3.y);
    }
    __syncthreads();

    float fv1 = 0.f, fv2 = 0.f;
    if (tid < 480) {                                  // warps 0..14, warp-aligned
#pragma unroll
        for (int gg = 0; gg < 8; gg++) fv2raw += s_red[gg * 480 + tid];
        const int c2i = tid & 7;
        float Asum = s_msc[c2i];
        float w2v  = __ldg(gw2 + tid);
        float cv   = __ldg(gcov + tid);
        float cw   = cv * cv + 1e-6f;
        fv1 = (fv1raw - Asum * w2v) / cw;
        fv2 = (Asum * w2v * w2v + fv2raw - 2.f * fv1raw * w2v) / (cw * cw) - Asum;

        float sq1 = fv1 * fv1;
        float sq2 = fv2 * fv2;
        sq1 += __shfl_xor_sync(0xffffffffu, sq1, 8);
        sq1 += __shfl_xor_sync(0xffffffffu, sq1, 16);
        sq2 += __shfl_xor_sync(0xffffffffu, sq2, 1);
        sq2 += __shfl_xor_sync(0xffffffffu, sq2, 2);
        sq2 += __shfl_xor_sync(0xffffffffu, sq2, 4);
        sq2 += __shfl_xor_sync(0xffffffffu, sq2, 8);
        sq2 += __shfl_xor_sync(0xffffffffu, sq2, 16);
        if (lane < 8)  s_q1p[w * 8 + lane] = sq1;
        if (lane == 0) s_q2p[w] = sq2;
    }
    __syncthreads();
    if (tid == 0) {
        float G = 0.f;
#pragma unroll
        for (int c = 0; c < 8; c++) {
            float q = 0.f;
#pragma unroll
            for (int ww = 0; ww < 15; ww++) q += s_q1p[ww * 8 + c];
            float r = rsqrtf(fmaxf(q, 1e-12f));
            s_msc[8 + c] = r;
            G += q * r * r;
        }
        s_msc[16] = rsqrtf(fmaxf(G, 1e-12f));
        float q2s = 0.f;
#pragma unroll
        for (int ww = 0; ww < 15; ww++) q2s += s_q2p[ww];
        float r2  = rsqrtf(fmaxf(q2s, 1e-12f));
        float q2b = q2s * r2 * r2;
        s_msc[17] = r2 * rsqrtf(fmaxf(q2b, 1e-12f));
    }
    __syncthreads();
    if (tid < 480) {
        s_fv[tid]       = fv1 * s_msc[8 + (tid & 7)] * s_msc[16];
        s_fv[480 + tid] = fv2 * s_msc[17];
    }
    __syncthreads();

    // final matvec: out[b,:] = fv(960) @ H(960x18)
    if (tid < 486) {
        int ggq = tid / 18;
        int o   = tid - ggq * 18;
        float acc = 0.f;
        for (int jj = ggq; jj < 960; jj += 27)
            acc += s_fv[jj] * gH[jj * 18 + o];
        s_pt[tid] = acc;
    }
    __syncthreads();
    if (tid < 18) {
        float s = 0.f;
#pragma unroll
        for (int ggq = 0; ggq < 27; ggq++) s += s_pt[ggq * 18 + tid];
        gout[b * OUTd + tid] = s;
    }
}

extern "C" void kernel_launch(void* const* d_in, const int* in_sizes, int n_in,
                              void* d_out, int out_size) {
    const float* x    = (const float*)d_in[0];
    const float* W    = (const float*)d_in[1];
    const float* cov  = (const float*)d_in[2];
    const float* bias = (const float*)d_in[3];
    const float* w2   = (const float*)d_in[4];
    const float* H    = (const float*)d_in[5];
    float* out = (float*)d_out;

    const int smem_bytes = SM_FLOATS * 4;   // ~108 KB
    cudaFuncSetAttribute(netfv_kernel, cudaFuncAttributeMaxDynamicSharedMemorySize, smem_bytes);

    int B = in_sizes[0] / (Mdim * Fdim);    // 2048
    netfv_kernel<<<B, NTHR, smem_bytes>>>(x, W, cov, bias, w2, H, out);
}

// round 15
// speedup vs baseline: 1.1471x; 1.0717x over previous
#include <cuda_runtime.h>

#define Fdim 60
#define Mdim 600
#define OUTd 18
#define NTHR 512
#define SR   68                 // x-tile row stride; 68 % 32 == 4 -> conflict-free patterns
#define XTSZ (120 * SR)         // 8160 floats per x buffer

typedef unsigned long long u64;

__device__ __forceinline__ u64 pk2(float x, float y) {
    u64 r; asm("mov.b64 %0,{%1,%2};" : "=l"(r) : "f"(x), "f"(y)); return r;
}
__device__ __forceinline__ float2 upk2(u64 v) {
    float2 r; asm("mov.b64 {%0,%1},%2;" : "=f"(r.x), "=f"(r.y) : "l"(v)); return r;
}
__device__ __forceinline__ u64 ffma2(u64 a, u64 b, u64 c) {
    u64 d; asm("fma.rn.f32x2 %0,%1,%2,%3;" : "=l"(d) : "l"(a), "l"(b), "l"(c)); return d;
}
__device__ __forceinline__ u64 fadd2(u64 a, u64 b) {
    u64 d; asm("add.rn.f32x2 %0,%1,%2;" : "=l"(d) : "l"(a), "l"(b)); return d;
}

// Distributed reduction over 4 lanes (xor 1,2): lane aj ends with accumulator aj
// fully reduced across its 4-lane group.
__device__ __forceinline__ u64 distred4(u64 a0, u64 a1, u64 a2, u64 a3, int aj) {
    u64 u = (aj & 1) ? a1 : a0;
    u64 v = (aj & 1) ? a0 : a1;
    u = fadd2(u, __shfl_xor_sync(0xffffffffu, v, 1));
    u64 w2 = (aj & 1) ? a3 : a2;
    u64 z  = (aj & 1) ? a2 : a3;
    w2 = fadd2(w2, __shfl_xor_sync(0xffffffffu, z, 1));
    u64 r = (aj & 2) ? w2 : u;
    u64 s = (aj & 2) ? u : w2;
    r = fadd2(r, __shfl_xor_sync(0xffffffffu, s, 2));
    return r;
}

// smem layout (floats): 3 x-buffers | 2 act buffers | W | apart | q1p | q2p | msc
#define SM_FLOATS (3 * XTSZ + 2 * 960 + 480 + 64 + 120 + 16 + 18)

__global__ __launch_bounds__(NTHR, 2)
void netfv_kernel(const float* __restrict__ gx,     // [B*600, 60]
                  const float* __restrict__ gW,     // [60, 8]
                  const float* __restrict__ gcov,   // [60, 8]
                  const float* __restrict__ gbias,  // [8]
                  const float* __restrict__ gw2,    // [60, 8]
                  const float* __restrict__ gH,     // [960, 18]
                  float* __restrict__ gout)         // [B, 18]
{
    extern __shared__ __align__(16) float sm[];
    float* bxa = sm;
    float* bxb = sm + XTSZ;
    float* bxc = sm + 2 * XTSZ;
    float* ac0 = sm + 3 * XTSZ;           // 960
    float* ac1 = ac0 + 960;               // 960
    float* sW  = ac1 + 960;               // 480
    float* s_apart = sW + 480;            // 64  (8 A-warps x 8c)
    float* s_q1p   = s_apart + 64;        // 120 (15 warps x 8c)
    float* s_q2p   = s_q1p + 120;         // 16
    float* s_msc   = s_q2p + 16;          // 18: [0..7]=asum,[8..15]=rc,[16]=rg,[17]=sc2

    const int tid  = threadIdx.x;
    const int b    = blockIdx.x;
    const int w    = tid >> 5;
    const int lane = tid & 31;

    if (tid < 480) sW[tid] = gW[tid];

    const float* xb = gx + (size_t)b * (Mdim * Fdim);

    // staging mapping on B-warps: stid = tid-256 (<240): elem e = stid+240j -> m=md+4j, f=fd
    const int stid  = tid - 256;
    const bool stgv = (w >= 8) && (stid < 240);
    const int md    = stgv ? stid / 60 : 0;
    const int fd    = stgv ? stid - md * 60 : 0;
    const int stoff = md * SR + fd;

    // prologue: B-warps stage chunk 0 into bxa
    if (stgv) {
        const float* src = xb + stid;
        float* dst = bxa + stoff;
#pragma unroll
        for (int jb = 0; jb < 3; jb++) {
            float t[10];
#pragma unroll
            for (int q = 0; q < 10; q++) t[q] = src[(jb * 10 + q) * 240];
#pragma unroll
            for (int q = 0; q < 10; q++) dst[(jb * 10 + q) * 4 * SR] = t[q];
        }
    }
    __syncthreads();

    // phase-A mapping (warps 0..7, all 256 threads run shfls):
    // rp = tid>>2 in 0..63, valid rows rp<60; rows rp and rp+60; aj = k-quarter
    const int rp   = tid >> 2;
    const int aj   = tid & 3;
    const bool rpv = (rp < 60);
    const int rpc  = rpv ? rp : 59;        // clamped for loads
    const float2 bp = __ldg((const float2*)gbias + aj);   // this lane's bias c-pair
    float asr0 = 0.f, asr1 = 0.f;

    // phase-B mapping: warps 8..15, g = w-8; lane (<30) owns f pair (2*lane, 2*lane+1)
    const int g  = w - 8;
    const int fl = lane;

    u64 c1a[4], c2a[4], c1b[4], c2b[4];
#pragma unroll
    for (int p = 0; p < 4; p++) { c1a[p]=0; c2a[p]=0; c1b[p]=0; c2b[p]=0; }

    float* xA = bxa;   // phase-A buffer (chunk it)
    float* xN = bxb;   // staging target (chunk it+1)
    float* xB = bxc;   // phase-B buffer (chunk it-1)

    for (int it = 0; it < 6; ++it) {
        float* acW = (it & 1) ? ac1 : ac0;
        float* acR = (it & 1) ? ac0 : ac1;

        if (w < 8) {
            // ---- phase A on chunk it (ALL 256 threads; guarded stores) ----
            if (it < 5) {
                u64 a0[4], a1[4];
#pragma unroll
                for (int p = 0; p < 4; p++) { a0[p] = 0; a1[p] = 0; }
                const float* x0 = xA + rpc * SR + aj;
                const float* x1 = x0 + 60 * SR;
#pragma unroll
                for (int i = 0; i < 15; i++) {
                    int kk = aj + 4 * i;               // interleaved k -> conflict-free
                    float xk0 = x0[4 * i];
                    float xk1 = x1[4 * i];
                    ulonglong2 wA = *(const ulonglong2*)&sW[kk * 8];
                    ulonglong2 wB = *(const ulonglong2*)&sW[kk * 8 + 4];
                    u64 X0 = pk2(xk0, xk0), X1 = pk2(xk1, xk1);
                    a0[0] = ffma2(X0, wA.x, a0[0]);  a1[0] = ffma2(X1, wA.x, a1[0]);
                    a0[1] = ffma2(X0, wA.y, a0[1]);  a1[1] = ffma2(X1, wA.y, a1[1]);
                    a0[2] = ffma2(X0, wB.x, a0[2]);  a1[2] = ffma2(X1, wB.x, a1[2]);
                    a0[3] = ffma2(X0, wB.y, a0[3]);  a1[3] = ffma2(X1, wB.y, a1[3]);
                }
                // distributed 4-lane reduction: lane aj owns c-pair (2aj, 2aj+1)
                u64 r0 = distred4(a0[0], a0[1], a0[2], a0[3], aj);
                u64 r1 = distred4(a1[0], a1[1], a1[2], a1[3], aj);
                // softmax (no max-sub: logits bounded, __expf safe)
                {
                    float2 p0 = upk2(r0);
                    float e0 = __expf(p0.x + bp.x);
                    float e1 = __expf(p0.y + bp.y);
                    float s2 = e0 + e1;
                    s2 += __shfl_xor_sync(0xffffffffu, s2, 1);
                    s2 += __shfl_xor_sync(0xffffffffu, s2, 2);
                    float inv = __fdividef(1.f, s2);
                    if (rpv) {
                        float v0 = e0 * inv, v1 = e1 * inv;
                        *(float2*)&acW[rp * 8 + 2 * aj] = make_float2(v0, v1);
                        asr0 += v0; asr1 += v1;
                    }
                }
                {
                    float2 p1 = upk2(r1);
                    float e0 = __expf(p1.x + bp.x);
                    float e1 = __expf(p1.y + bp.y);
                    float s2 = e0 + e1;
                    s2 += __shfl_xor_sync(0xffffffffu, s2, 1);
                    s2 += __shfl_xor_sync(0xffffffffu, s2, 2);
                    float inv = __fdividef(1.f, s2);
                    if (rpv) {
                        float v0 = e0 * inv, v1 = e1 * inv;
                        *(float2*)&acW[(rp + 60) * 8 + 2 * aj] = make_float2(v0, v1);
                        asr0 += v0; asr1 += v1;
                    }
                }
            }
        } else {
            // ---- stage chunk it+1 (B-warps; LDG latency hides behind phase B below) ----
            if (it < 4 && stid < 240) {
                const float* src = xb + (it + 1) * 7200 + stid;
                float* dst = xN + stoff;
#pragma unroll
                for (int jb = 0; jb < 3; jb++) {
                    float t[10];
#pragma unroll
                    for (int q = 0; q < 10; q++) t[q] = src[(jb * 10 + q) * 240];
#pragma unroll
                    for (int q = 0; q < 10; q++) dst[(jb * 10 + q) * 4 * SR] = t[q];
                }
            }
            // ---- phase B on chunk it-1: fv1/fv2, adjacent f-pair, x via LDS.64 ----
            if (it >= 1 && lane < 30) {
#pragma unroll
                for (int i = 0; i < 15; i++) {
                    int m = g + 8 * i;
                    ulonglong2 A01 = *(const ulonglong2*)&acR[m * 8];
                    ulonglong2 A23 = *(const ulonglong2*)&acR[m * 8 + 4];
                    float2 xp = *(const float2*)&xB[m * SR + 2 * fl];   // one LDS.64
                    float xa = xp.x, xv = xp.y;
                    u64 XA = pk2(xa, xa), XB = pk2(xv, xv);
                    float qa = xa * xa, qb = xv * xv;
                    u64 QA = pk2(qa, qa), QB = pk2(qb, qb);
                    c1a[0] = ffma2(A01.x, XA, c1a[0]);  c2a[0] = ffma2(A01.x, QA, c2a[0]);
                    c1a[1] = ffma2(A01.y, XA, c1a[1]);  c2a[1] = ffma2(A01.y, QA, c2a[1]);
                    c1a[2] = ffma2(A23.x, XA, c1a[2]);  c2a[2] = ffma2(A23.x, QA, c2a[2]);
                    c1a[3] = ffma2(A23.y, XA, c1a[3]);  c2a[3] = ffma2(A23.y, QA, c2a[3]);
                    c1b[0] = ffma2(A01.x, XB, c1b[0]);  c2b[0] = ffma2(A01.x, QB, c2b[0]);
                    c1b[1] = ffma2(A01.y, XB, c1b[1]);  c2b[1] = ffma2(A01.y, QB, c2b[1]);
                    c1b[2] = ffma2(A23.x, XB, c1b[2]);  c2b[2] = ffma2(A23.x, QB, c2b[2]);
                    c1b[3] = ffma2(A23.y, XB, c1b[3]);  c2b[3] = ffma2(A23.y, QB, c2b[3]);
                }
            }
        }
        __syncthreads();
        // rotate x buffers: {A, N, B} <- {N, B, A}
        float* t = xA; xA = xN; xN = xB; xB = t;
    }

    // ================= epilogue =================
    float* s_red = bxa;            // 3840
    float* s_fv  = bxa + 3840;     // 960
    float* s_pt  = bxa + 4800;     // 486

    // a_sum partials from A-warps (ALL 256 threads run the shfls)
    if (w < 8) {
        float r0 = asr0, r1 = asr1;
        r0 += __shfl_xor_sync(0xffffffffu, r0, 4);
        r1 += __shfl_xor_sync(0xffffffffu, r1, 4);
        r0 += __shfl_xor_sync(0xffffffffu, r0, 8);
        r1 += __shfl_xor_sync(0xffffffffu, r1, 8);
        r0 += __shfl_xor_sync(0xffffffffu, r0, 16);
        r1 += __shfl_xor_sync(0xffffffffu, r1, 16);
        if (lane < 4) {
            s_apart[w * 8 + 2 * aj]     = r0;
            s_apart[w * 8 + 2 * aj + 1] = r1;
        }
    }
    // dump acc1 for both f (adjacent pair 2fl, 2fl+1)
    if (w >= 8 && lane < 30) {
        int vt0 = g * 60 + 2 * fl;
        float2 q0 = upk2(c1a[0]), q1 = upk2(c1a[1]), q2v = upk2(c1a[2]), q3 = upk2(c1a[3]);
        float4* rp0 = (float4*)&s_red[vt0 * 8];
        rp0[0] = make_float4(q0.x, q0.y, q1.x, q1.y);
        rp0[1] = make_float4(q2v.x, q2v.y, q3.x, q3.y);
        q0 = upk2(c1b[0]); q1 = upk2(c1b[1]); q2v = upk2(c1b[2]); q3 = upk2(c1b[3]);
        float4* rp1 = (float4*)&s_red[(vt0 + 1) * 8];
        rp1[0] = make_float4(q0.x, q0.y, q1.x, q1.y);
        rp1[1] = make_float4(q2v.x, q2v.y, q3.x, q3.y);
    }
    __syncthreads();
    if (tid < 8) {
        float A = 0.f;
#pragma unroll
        for (int ww = 0; ww < 8; ww++) A += s_apart[ww * 8 + tid];
        s_msc[tid] = A;
    }
    float fv1raw = 0.f, fv2raw = 0.f;
    if (tid < 480) {
#pragma unroll
        for (int gg = 0; gg < 8; gg++) fv1raw += s_red[gg * 480 + tid];
    }
    __syncthreads();
    if (w >= 8 && lane < 30) {
        int vt0 = g * 60 + 2 * fl;
        float2 q0 = upk2(c2a[0]), q1 = upk2(c2a[1]), q2v = upk2(c2a[2]), q3 = upk2(c2a[3]);
        float4* rp0 = (float4*)&s_red[vt0 * 8];
        rp0[0] = make_float4(q0.x, q0.y, q1.x, q1.y);
        rp0[1] = make_float4(q2v.x, q2v.y, q3.x, q3.y);
        q0 = upk2(c2b[0]); q1 = upk2(c2b[1]); q2v = upk2(c2b[2]); q3 = upk2(c2b[3]);
        float4* rp1 = (float4*)&s_red[(vt0 + 1) * 8];
        rp1[0] = make_float4(q0.x, q0.y, q1.x, q1.y);
        rp1[1] = make_float4(q2v.x, q2v.y, q3.x, q3.y);
    }
    __syncthreads();

    float fv1 = 0.f, fv2 = 0.f;
    if (tid < 480) {                                  // warps 0..14, warp-aligned
#pragma unroll
        for (int gg = 0; gg < 8; gg++) fv2raw += s_red[gg * 480 + tid];
        const int c2i = tid & 7;
        float Asum = s_msc[c2i];
        float w2v  = __ldg(gw2 + tid);
        float cv   = __ldg(gcov + tid);
        float cw   = cv * cv + 1e-6f;
        fv1 = (fv1raw - Asum * w2v) / cw;
        fv2 = (Asum * w2v * w2v + fv2raw - 2.f * fv1raw * w2v) / (cw * cw) - Asum;

        float sq1 = fv1 * fv1;
        float sq2 = fv2 * fv2;
        sq1 += __shfl_xor_sync(0xffffffffu, sq1, 8);
        sq1 += __shfl_xor_sync(0xffffffffu, sq1, 16);
        sq2 += __shfl_xor_sync(0xffffffffu, sq2, 1);
        sq2 += __shfl_xor_sync(0xffffffffu, sq2, 2);
        sq2 += __shfl_xor_sync(0xffffffffu, sq2, 4);
        sq2 += __shfl_xor_sync(0xffffffffu, sq2, 8);
        sq2 += __shfl_xor_sync(0xffffffffu, sq2, 16);
        if (lane < 8)  s_q1p[w * 8 + lane] = sq1;
        if (lane == 0) s_q2p[w] = sq2;
    }
    __syncthreads();
    if (tid == 0) {
        float G = 0.f;
#pragma unroll
        for (int c = 0; c < 8; c++) {
            float q = 0.f;
#pragma unroll
            for (int ww = 0; ww < 15; ww++) q += s_q1p[ww * 8 + c];
            float r = rsqrtf(fmaxf(q, 1e-12f));
            s_msc[8 + c] = r;
            G += q * r * r;
        }
        s_msc[16] = rsqrtf(fmaxf(G, 1e-12f));
        float q2s = 0.f;
#pragma unroll
        for (int ww = 0; ww < 15; ww++) q2s += s_q2p[ww];
        float r2  = rsqrtf(fmaxf(q2s, 1e-12f));
        float q2b = q2s * r2 * r2;
        s_msc[17] = r2 * rsqrtf(fmaxf(q2b, 1e-12f));
    }
    __syncthreads();
    if (tid < 480) {
        s_fv[tid]       = fv1 * s_msc[8 + (tid & 7)] * s_msc[16];
        s_fv[480 + tid] = fv2 * s_msc[17];
    }
    __syncthreads();

    // final matvec: out[b,:] = fv(960) @ H(960x18)
    if (tid < 486) {
        int ggq = tid / 18;
        int o   = tid - ggq * 18;
        float acc = 0.f;
        for (int jj = ggq; jj < 960; jj += 27)
            acc += s_fv[jj] * gH[jj * 18 + o];
        s_pt[tid] = acc;
    }
    __syncthreads();
    if (tid < 18) {
        float s = 0.f;
#pragma unroll
        for (int ggq = 0; ggq < 27; ggq++) s += s_pt[ggq * 18 + tid];
        gout[b * OUTd + tid] = s;
    }
}

extern "C" void kernel_launch(void* const* d_in, const int* in_sizes, int n_in,
                              void* d_out, int out_size) {
    const float* x    = (const float*)d_in[0];
    const float* W    = (const float*)d_in[1];
    const float* cov  = (const float*)d_in[2];
    const float* bias = (const float*)d_in[3];
    const float* w2   = (const float*)d_in[4];
    const float* H    = (const float*)d_in[5];
    float* out = (float*)d_out;

    const int smem_bytes = SM_FLOATS * 4;   // ~108 KB
    cudaFuncSetAttribute(netfv_kernel, cudaFuncAttributeMaxDynamicSharedMemorySize, smem_bytes);

    int B = in_sizes[0] / (Mdim * Fdim);    // 2048
    netfv_kernel<<<B, NTHR, smem_bytes>>>(x, W, cov, bias, w2, H, out);
}

// round 16
// speedup vs baseline: 1.1479x; 1.0008x over previous
#include <cuda_runtime.h>

#define Fdim 60
#define Mdim 600
#define OUTd 18
#define NTHR 512
#define SR   68                 // x-tile row stride; 68 % 32 == 4 -> conflict-free patterns
#define XTSZ (120 * SR)         // 8160 floats per x buffer

typedef unsigned long long u64;

__device__ __forceinline__ u64 pk2(float x, float y) {
    u64 r; asm("mov.b64 %0,{%1,%2};" : "=l"(r) : "f"(x), "f"(y)); return r;
}
__device__ __forceinline__ float2 upk2(u64 v) {
    float2 r; asm("mov.b64 {%0,%1},%2;" : "=f"(r.x), "=f"(r.y) : "l"(v)); return r;
}
__device__ __forceinline__ u64 ffma2(u64 a, u64 b, u64 c) {
    u64 d; asm("fma.rn.f32x2 %0,%1,%2,%3;" : "=l"(d) : "l"(a), "l"(b), "l"(c)); return d;
}
__device__ __forceinline__ u64 fadd2(u64 a, u64 b) {
    u64 d; asm("add.rn.f32x2 %0,%1,%2;" : "=l"(d) : "l"(a), "l"(b)); return d;
}
__device__ __forceinline__ u64 fmul2(u64 a, u64 b) {
    u64 d; asm("mul.rn.f32x2 %0,%1,%2;" : "=l"(d) : "l"(a), "l"(b)); return d;
}

// Distributed reduction over 4 lanes (xor 1,2): lane aj ends with accumulator aj
// fully reduced across its 4-lane group.
__device__ __forceinline__ u64 distred4(u64 a0, u64 a1, u64 a2, u64 a3, int aj) {
    u64 u = (aj & 1) ? a1 : a0;
    u64 v = (aj & 1) ? a0 : a1;
    u = fadd2(u, __shfl_xor_sync(0xffffffffu, v, 1));
    u64 w2 = (aj & 1) ? a3 : a2;
    u64 z  = (aj & 1) ? a2 : a3;
    w2 = fadd2(w2, __shfl_xor_sync(0xffffffffu, z, 1));
    u64 r = (aj & 2) ? w2 : u;
    u64 s = (aj & 2) ? u : w2;
    r = fadd2(r, __shfl_xor_sync(0xffffffffu, s, 2));
    return r;
}

// smem layout (floats): 3 x-buffers | 2 act buffers | W | apart | q1p | q2p | msc
#define SM_FLOATS (3 * XTSZ + 2 * 960 + 480 + 64 + 120 + 16 + 18)

__global__ __launch_bounds__(NTHR, 2)
void netfv_kernel(const float* __restrict__ gx,     // [B*600, 60]
                  const float* __restrict__ gW,     // [60, 8]
                  const float* __restrict__ gcov,   // [60, 8]
                  const float* __restrict__ gbias,  // [8]
                  const float* __restrict__ gw2,    // [60, 8]
                  const float* __restrict__ gH,     // [960, 18]
                  float* __restrict__ gout)         // [B, 18]
{
    extern __shared__ __align__(16) float sm[];
    float* bxa = sm;
    float* bxb = sm + XTSZ;
    float* bxc = sm + 2 * XTSZ;
    float* ac0 = sm + 3 * XTSZ;           // 960
    float* ac1 = ac0 + 960;               // 960
    float* sW  = ac1 + 960;               // 480
    float* s_apart = sW + 480;            // 64  (8 A-warps x 8c)
    float* s_q1p   = s_apart + 64;        // 120 (15 warps x 8c)
    float* s_q2p   = s_q1p + 120;         // 16
    float* s_msc   = s_q2p + 16;          // 18: [0..7]=asum,[8..15]=rc,[16]=rg,[17]=sc2

    const int tid  = threadIdx.x;
    const int b    = blockIdx.x;
    const int w    = tid >> 5;
    const int lane = tid & 31;

    if (tid < 480) sW[tid] = gW[tid];

    const float* xb = gx + (size_t)b * (Mdim * Fdim);

    // staging mapping on B-warps (float2): stid = tid-256 (<240);
    // elem pair e = 2*stid + 480j -> m = stid/30 + 8j, f = 2*(stid%30) (+1), j=0..14
    const int stid  = tid - 256;
    const bool stgv = (w >= 8) && (stid < 240);
    const int md2   = stgv ? stid / 30 : 0;
    const int fd2   = stgv ? 2 * (stid - md2 * 30) : 0;
    const int stoff = md2 * SR + fd2;          // smem float offset of j=0 pair

    // prologue: B-warps stage chunk 0 into bxa (float2)
    if (stgv) {
        const float2* src = (const float2*)xb + stid;
        float* dst = bxa + stoff;
#pragma unroll
        for (int jb = 0; jb < 3; jb++) {
            float2 t[5];
#pragma unroll
            for (int q = 0; q < 5; q++) t[q] = src[(jb * 5 + q) * 240];
#pragma unroll
            for (int q = 0; q < 5; q++)
                *(float2*)&dst[(jb * 5 + q) * 8 * SR] = t[q];
        }
    }
    __syncthreads();

    // phase-A mapping (warps 0..7, all 256 threads run shfls):
    // rp = tid>>2 in 0..63, valid rows rp<60; rows rp and rp+60; aj = k-quarter
    const int rp   = tid >> 2;
    const int aj   = tid & 3;
    const bool rpv = (rp < 60);
    const int rpc  = rpv ? rp : 59;        // clamped for loads
    const float2 bp = __ldg((const float2*)gbias + aj);   // this lane's bias c-pair
    float asr0 = 0.f, asr1 = 0.f;

    // phase-B mapping: warps 8..15, g = w-8; lane (<30) owns f pair (2*lane, 2*lane+1)
    const int g  = w - 8;
    const int fl = lane;

    u64 c1a[4], c2a[4], c1b[4], c2b[4];
#pragma unroll
    for (int p = 0; p < 4; p++) { c1a[p]=0; c2a[p]=0; c1b[p]=0; c2b[p]=0; }

    float* xA = bxa;   // phase-A buffer (chunk it)
    float* xN = bxb;   // staging target (chunk it+1)
    float* xB = bxc;   // phase-B buffer (chunk it-1)

    for (int it = 0; it < 6; ++it) {
        float* acW = (it & 1) ? ac1 : ac0;
        float* acR = (it & 1) ? ac0 : ac1;

        if (w < 8) {
            // ---- phase A on chunk it (ALL 256 threads; guarded stores) ----
            if (it < 5) {
                u64 a0[4], a1[4];
#pragma unroll
                for (int p = 0; p < 4; p++) { a0[p] = 0; a1[p] = 0; }
                const float* x0 = xA + rpc * SR + aj;
                const float* x1 = x0 + 60 * SR;
#pragma unroll
                for (int i = 0; i < 15; i++) {
                    int kk = aj + 4 * i;               // interleaved k -> conflict-free
                    float xk0 = x0[4 * i];
                    float xk1 = x1[4 * i];
                    ulonglong2 wA = *(const ulonglong2*)&sW[kk * 8];
                    ulonglong2 wB = *(const ulonglong2*)&sW[kk * 8 + 4];
                    u64 X0 = pk2(xk0, xk0), X1 = pk2(xk1, xk1);
                    a0[0] = ffma2(X0, wA.x, a0[0]);  a1[0] = ffma2(X1, wA.x, a1[0]);
                    a0[1] = ffma2(X0, wA.y, a0[1]);  a1[1] = ffma2(X1, wA.y, a1[1]);
                    a0[2] = ffma2(X0, wB.x, a0[2]);  a1[2] = ffma2(X1, wB.x, a1[2]);
                    a0[3] = ffma2(X0, wB.y, a0[3]);  a1[3] = ffma2(X1, wB.y, a1[3]);
                }
                // distributed 4-lane reduction: lane aj owns c-pair (2aj, 2aj+1)
                u64 r0 = distred4(a0[0], a0[1], a0[2], a0[3], aj);
                u64 r1 = distred4(a1[0], a1[1], a1[2], a1[3], aj);
                // softmax (no max-sub: logits bounded, __expf safe)
                {
                    float2 p0 = upk2(r0);
                    float e0 = __expf(p0.x + bp.x);
                    float e1 = __expf(p0.y + bp.y);
                    float s2 = e0 + e1;
                    s2 += __shfl_xor_sync(0xffffffffu, s2, 1);
                    s2 += __shfl_xor_sync(0xffffffffu, s2, 2);
                    float inv = __fdividef(1.f, s2);
                    if (rpv) {
                        float v0 = e0 * inv, v1 = e1 * inv;
                        *(float2*)&acW[rp * 8 + 2 * aj] = make_float2(v0, v1);
                        asr0 += v0; asr1 += v1;
                    }
                }
                {
                    float2 p1 = upk2(r1);
                    float e0 = __expf(p1.x + bp.x);
                    float e1 = __expf(p1.y + bp.y);
                    float s2 = e0 + e1;
                    s2 += __shfl_xor_sync(0xffffffffu, s2, 1);
                    s2 += __shfl_xor_sync(0xffffffffu, s2, 2);
                    float inv = __fdividef(1.f, s2);
                    if (rpv) {
                        float v0 = e0 * inv, v1 = e1 * inv;
                        *(float2*)&acW[(rp + 60) * 8 + 2 * aj] = make_float2(v0, v1);
                        asr0 += v0; asr1 += v1;
                    }
                }
            }
        } else {
            // ---- stage chunk it+1 (B-warps, float2; latency hides behind phase B) ----
            if (it < 4 && stid < 240) {
                const float2* src = (const float2*)(xb + (it + 1) * 7200) + stid;
                float* dst = xN + stoff;
#pragma unroll
                for (int jb = 0; jb < 3; jb++) {
                    float2 t[5];
#pragma unroll
                    for (int q = 0; q < 5; q++) t[q] = src[(jb * 5 + q) * 240];
#pragma unroll
                    for (int q = 0; q < 5; q++)
                        *(float2*)&dst[(jb * 5 + q) * 8 * SR] = t[q];
                }
            }
            // ---- phase B on chunk it-1: fv1/fv2, adjacent f-pair, x via LDS.64 ----
            if (it >= 1 && lane < 30) {
#pragma unroll
                for (int i = 0; i < 15; i++) {
                    int m = g + 8 * i;
                    ulonglong2 A01 = *(const ulonglong2*)&acR[m * 8];
                    ulonglong2 A23 = *(const ulonglong2*)&acR[m * 8 + 4];
                    float2 xp = *(const float2*)&xB[m * SR + 2 * fl];   // one LDS.64
                    u64 XA = pk2(xp.x, xp.x), XB = pk2(xp.y, xp.y);
                    u64 QA = fmul2(XA, XA);                              // packed squares
                    u64 QB = fmul2(XB, XB);
                    c1a[0] = ffma2(A01.x, XA, c1a[0]);  c2a[0] = ffma2(A01.x, QA, c2a[0]);
                    c1a[1] = ffma2(A01.y, XA, c1a[1]);  c2a[1] = ffma2(A01.y, QA, c2a[1]);
                    c1a[2] = ffma2(A23.x, XA, c1a[2]);  c2a[2] = ffma2(A23.x, QA, c2a[2]);
                    c1a[3] = ffma2(A23.y, XA, c1a[3]);  c2a[3] = ffma2(A23.y, QA, c2a[3]);
                    c1b[0] = ffma2(A01.x, XB, c1b[0]);  c2b[0] = ffma2(A01.x, QB, c2b[0]);
                    c1b[1] = ffma2(A01.y, XB, c1b[1]);  c2b[1] = ffma2(A01.y, QB, c2b[1]);
                    c1b[2] = ffma2(A23.x, XB, c1b[2]);  c2b[2] = ffma2(A23.x, QB, c2b[2]);
                    c1b[3] = ffma2(A23.y, XB, c1b[3]);  c2b[3] = ffma2(A23.y, QB, c2b[3]);
                }
            }
        }
        __syncthreads();
        // rotate x buffers: {A, N, B} <- {N, B, A}
        float* t = xA; xA = xN; xN = xB; xB = t;
    }

    // ================= epilogue =================
    float* s_red = bxa;            // 3840
    float* s_fv  = bxa + 3840;     // 960
    float* s_pt  = bxa + 4800;     // 486

    // a_sum partials from A-warps (ALL 256 threads run the shfls)
    if (w < 8) {
        float r0 = asr0, r1 = asr1;
        r0 += __shfl_xor_sync(0xffffffffu, r0, 4);
        r1 += __shfl_xor_sync(0xffffffffu, r1, 4);
        r0 += __shfl_xor_sync(0xffffffffu, r0, 8);
        r1 += __shfl_xor_sync(0xffffffffu, r1, 8);
        r0 += __shfl_xor_sync(0xffffffffu, r0, 16);
        r1 += __shfl_xor_sync(0xffffffffu, r1, 16);
        if (lane < 4) {
            s_apart[w * 8 + 2 * aj]     = r0;
            s_apart[w * 8 + 2 * aj + 1] = r1;
        }
    }
    // dump acc1 for both f (adjacent pair 2fl, 2fl+1)
    if (w >= 8 && lane < 30) {
        int vt0 = g * 60 + 2 * fl;
        float2 q0 = upk2(c1a[0]), q1 = upk2(c1a[1]), q2v = upk2(c1a[2]), q3 = upk2(c1a[3]);
        float4* rp0 = (float4*)&s_red[vt0 * 8];
        rp0[0] = make_float4(q0.x, q0.y, q1.x, q1.y);
        rp0[1] = make_float4(q2v.x, q2v.y, q3.x, q3.y);
        q0 = upk2(c1b[0]); q1 = upk2(c1b[1]); q2v = upk2(c1b[2]); q3 = upk2(c1b[3]);
        float4* rp1 = (float4*)&s_red[(vt0 + 1) * 8];
        rp1[0] = make_float4(q0.x, q0.y, q1.x, q1.y);
        rp1[1] = make_float4(q2v.x, q2v.y, q3.x, q3.y);
    }
    __syncthreads();
    if (tid < 8) {
        float A = 0.f;
#pragma unroll
        for (int ww = 0; ww < 8; ww++) A += s_apart[ww * 8 + tid];
        s_msc[tid] = A;
    }
    float fv1raw = 0.f, fv2raw = 0.f;
    if (tid < 480) {
#pragma unroll
        for (int gg = 0; gg < 8; gg++) fv1raw += s_red[gg * 480 + tid];
    }
    __syncthreads();
    if (w >= 8 && lane < 30) {
        int vt0 = g * 60 + 2 * fl;
        float2 q0 = upk2(c2a[0]), q1 = upk2(c2a[1]), q2v = upk2(c2a[2]), q3 = upk2(c2a[3]);
        float4* rp0 = (float4*)&s_red[vt0 * 8];
        rp0[0] = make_float4(q0.x, q0.y, q1.x, q1.y);
        rp0[1] = make_float4(q2v.x, q2v.y, q3.x, q3.y);
        q0 = upk2(c2b[0]); q1 = upk2(c2b[1]); q2v = upk2(c2b[2]); q3 = upk2(c2b[3]);
        float4* rp1 = (float4*)&s_red[(vt0 + 1) * 8];
        rp1[0] = make_float4(q0.x, q0.y, q1.x, q1.y);
        rp1[1] = make_float4(q2v.x, q2v.y, q3.x, q3.y);
    }
    __syncthreads();

    float fv1 = 0.f, fv2 = 0.f;
    if (tid < 480) {                                  // warps 0..14, warp-aligned
#pragma unroll
        for (int gg = 0; gg < 8; gg++) fv2raw += s_red[gg * 480 + tid];
        const int c2i = tid & 7;
        float Asum = s_msc[c2i];
        float w2v  = __ldg(gw2 + tid);
        float cv   = __ldg(gcov + tid);
        float cw   = cv * cv + 1e-6f;
        fv1 = (fv1raw - Asum * w2v) / cw;
        fv2 = (Asum * w2v * w2v + fv2raw - 2.f * fv1raw * w2v) / (cw * cw) - Asum;

        float sq1 = fv1 * fv1;
        float sq2 = fv2 * fv2;
        sq1 += __shfl_xor_sync(0xffffffffu, sq1, 8);
        sq1 += __shfl_xor_sync(0xffffffffu, sq1, 16);
        sq2 += __shfl_xor_sync(0xffffffffu, sq2, 1);
        sq2 += __shfl_xor_sync(0xffffffffu, sq2, 2);
        sq2 += __shfl_xor_sync(0xffffffffu, sq2, 4);
        sq2 += __shfl_xor_sync(0xffffffffu, sq2, 8);
        sq2 += __shfl_xor_sync(0xffffffffu, sq2, 16);
        if (lane < 8)  s_q1p[w * 8 + lane] = sq1;
        if (lane == 0) s_q2p[w] = sq2;
    }
    __syncthreads();
    if (tid == 0) {
        float G = 0.f;
#pragma unroll
        for (int c = 0; c < 8; c++) {
            float q = 0.f;
#pragma unroll
            for (int ww = 0; ww < 15; ww++) q += s_q1p[ww * 8 + c];
            float r = rsqrtf(fmaxf(q, 1e-12f));
            s_msc[8 + c] = r;
            G += q * r * r;
        }
        s_msc[16] = rsqrtf(fmaxf(G, 1e-12f));
        float q2s = 0.f;
#pragma unroll
        for (int ww = 0; ww < 15; ww++) q2s += s_q2p[ww];
        float r2  = rsqrtf(fmaxf(q2s, 1e-12f));
        float q2b = q2s * r2 * r2;
        s_msc[17] = r2 * rsqrtf(fmaxf(q2b, 1e-12f));
    }
    __syncthreads();
    if (tid < 480) {
        s_fv[tid]       = fv1 * s_msc[8 + (tid & 7)] * s_msc[16];
        s_fv[480 + tid] = fv2 * s_msc[17];
    }
    __syncthreads();

    // final matvec: out[b,:] = fv(960) @ H(960x18)
    if (tid < 486) {
        int ggq = tid / 18;
        int o   = tid - ggq * 18;
        float acc = 0.f;
        for (int jj = ggq; jj < 960; jj += 27)
            acc += s_fv[jj] * gH[jj * 18 + o];
        s_pt[tid] = acc;
    }
    __syncthreads();
    if (tid < 18) {
        float s = 0.f;
#pragma unroll
        for (int ggq = 0; ggq < 27; ggq++) s += s_pt[ggq * 18 + tid];
        gout[b * OUTd + tid] = s;
    }
}

extern "C" void kernel_launch(void* const* d_in, const int* in_sizes, int n_in,
                              void* d_out, int out_size) {
    const float* x    = (const float*)d_in[0];
    const float* W    = (const float*)d_in[1];
    const float* cov  = (const float*)d_in[2];
    const float* bias = (const float*)d_in[3];
    const float* w2   = (const float*)d_in[4];
    const float* H    = (const float*)d_in[5];
    float* out = (float*)d_out;

    const int smem_bytes = SM_FLOATS * 4;   // ~108 KB
    cudaFuncSetAttribute(netfv_kernel, cudaFuncAttributeMaxDynamicSharedMemorySize, smem_bytes);

    int B = in_sizes[0] / (Mdim * Fdim);    // 2048
    netfv_kernel<<<B, NTHR, smem_bytes>>>(x, W, cov, bias, w2, H, out);
}